// round 14
// baseline (speedup 1.0000x reference)
#include <cuda_runtime.h>
#include <cuda_fp16.h>
#include <math.h>
#include <stdint.h>

#define W_ 192
#define H_ 192
#define D_ 160
#define HW_ (H_ * W_)
#define NPAIRS  82             /* 164 planes = D + 4 halo */
#define NBLOCKS (6 * 24 * 2)

#define NTHREADS 192
#define NPROD    128

#define BAR_FULL0  1
#define BAR_FULL1  2
#define BAR_EMPTY0 3
#define BAR_EMPTY1 4
#define BAR_PROD   5

// tile geometry: 32 x 8 outputs, halo 36 x 12
#define HROWS 12
#define TROWF 480              /* floats per img plane: 12*40 */
#define TPLANEF 960            /* floats per plane (2 imgs) */
#define TPAIRF 1920            /* floats per pair buffer */
#define NPAIRS_LD 432          /* 12*18*2 8B pairs per plane */

// rs layout (plane-interleaved): [ch(5)][row(12)][x2(16)][plane(2)] of __half2
#define RSCH 384
#define RSROW 32
#define RSQ 1920

__device__ double   g_acc;
__device__ unsigned g_cnt;

static __device__ __forceinline__ void bar_sync_n(int id, int cnt) {
    asm volatile("bar.sync %0, %1;" :: "r"(id), "r"(cnt) : "memory");
}
static __device__ __forceinline__ void bar_arrive_n(int id, int cnt) {
    asm volatile("bar.arrive %0, %1;" :: "r"(id), "r"(cnt) : "memory");
}
static __device__ __forceinline__ void cp_async8(uint32_t dst, const float* src,
                                                 unsigned srcsz) {
    asm volatile("cp.async.ca.shared.global [%0], [%1], 8, %2;"
                 :: "r"(dst), "l"(src), "r"(srcsz) : "memory");
}
static __device__ __forceinline__ void cp_commit() {
    asm volatile("cp.async.commit_group;" ::: "memory");
}
static __device__ __forceinline__ void cp_wait2() {
    asm volatile("cp.async.wait_group 2;" ::: "memory");
}
// 8B shared load of two adjacent half2 (plane0, plane1)
static __device__ __forceinline__ void lds_h2x2(const __half2* p,
                                                __half2& a, __half2& b) {
    uint2 u = *reinterpret_cast<const uint2*>(p);
    a = *reinterpret_cast<__half2*>(&u.x);
    b = *reinterpret_cast<__half2*>(&u.y);
}

__global__ void __launch_bounds__(NTHREADS, 2)
lncc_k(const float* __restrict__ src, const float* __restrict__ tgt,
       float* __restrict__ out)
{
    __shared__ float tile[3][2][2][HROWS][40];
    __shared__ __align__(16) __half2 rs[2][RSQ];
    __shared__ float wsum[6];

    const int tid = threadIdx.x;
    const int x0  = blockIdx.x * 32;
    const int y0  = blockIdx.y * 8;
    const int b   = blockIdx.z;          // one z-chunk covers all of D
    const int zstart = -2;

    const float* baseS = src + (size_t)b * (D_ * HW_);
    const float* baseT = tgt + (size_t)b * (D_ * HW_);

    float acc = 0.f;

    if (tid < NPROD) {
        // ========================= PRODUCER (128) =========================
        uint32_t soffb[4];
        const float* gbase[4];
        unsigned vmask = 0, umask = 0;
        #pragma unroll
        for (int sl = 0; sl < 4; sl++) {
            soffb[sl] = 0; gbase[sl] = baseS;
            const int i = tid + NPROD * sl;
            if (i < NPAIRS_LD) {
                umask |= 1u << sl;
                const int img = (i >= 216) ? 1 : 0;
                const int j   = i - img * 216;
                const int row = j / 18;
                const int pc  = j - row * 18;
                soffb[sl] = (uint32_t)(img * TROWF + row * 40 + pc * 2) * 4u;
                const int gy = y0 + row - 2;
                const int gx = x0 + pc * 2 - 2;
                const bool v = ((unsigned)gy < (unsigned)H_) &&
                               ((unsigned)gx < (unsigned)W_);
                if (v) vmask |= 1u << sl;
                gbase[sl] = (img ? baseT : baseS) + (v ? (gy * W_ + gx) : 0);
            }
        }

        const uint32_t sbase =
            (uint32_t)__cvta_generic_to_shared(&tile[0][0][0][0][0]);

        auto issue_pair = [&](int m) {
            const uint32_t pb = sbase + (uint32_t)(m % 3) * (TPAIRF * 4u);
            #pragma unroll
            for (int pl = 0; pl < 2; pl++) {
                const int zp   = zstart + 2 * m + pl;
                const bool zin = (unsigned)zp < (unsigned)D_;
                const int zoff = zin ? zp * HW_ : 0;
                const uint32_t tb = pb + (uint32_t)pl * (TPLANEF * 4u);
                #pragma unroll
                for (int sl = 0; sl < 4; sl++) {
                    if (umask & (1u << sl)) {
                        unsigned sz = (zin && (vmask & (1u << sl))) ? 8u : 0u;
                        cp_async8(tb + soffb[sl], gbase[sl] + zoff, sz);
                    }
                }
            }
            cp_commit();
        };

        // x-phase item covering BOTH planes of (row r, group g)
        auto xpair = [&](const float* pbuf, __half2* rsq, int item) {
            const int r = item >> 3;
            const int g = item & 7;
            const float* base0 = pbuf + r * 40 + 4 * g;
            __half2 keep[5][2];
            #pragma unroll
            for (int pl = 0; pl < 2; pl++) {
                const float* rowS = base0 + pl * TPLANEF;
                const float* rowT = rowS + TROWF;
                float4 a0 = *(const float4*)(rowS);
                float4 a1 = *(const float4*)(rowS + 4);
                float4 b0 = *(const float4*)(rowT);
                float4 b1 = *(const float4*)(rowT + 4);
                float sc[8] = {a0.x,a0.y,a0.z,a0.w,a1.x,a1.y,a1.z,a1.w};
                float tc[8] = {b0.x,b0.y,b0.z,b0.w,b1.x,b1.y,b1.z,b1.w};

                float V[5][4];
                {
                    float S0=0.f, T0=0.f, SS0=0.f, TT0=0.f, ST0=0.f;
                    #pragma unroll
                    for (int j = 0; j < 5; j++) {
                        S0 += sc[j]; T0 += tc[j];
                        SS0 = fmaf(sc[j], sc[j], SS0);
                        TT0 = fmaf(tc[j], tc[j], TT0);
                        ST0 = fmaf(sc[j], tc[j], ST0);
                    }
                    V[0][0]=S0; V[1][0]=T0; V[2][0]=SS0; V[3][0]=TT0; V[4][0]=ST0;
                    #pragma unroll
                    for (int w = 1; w < 4; w++) {
                        V[0][w] = V[0][w-1] - sc[w-1] + sc[w+4];
                        V[1][w] = V[1][w-1] - tc[w-1] + tc[w+4];
                        V[2][w] = V[2][w-1] - sc[w-1]*sc[w-1] + sc[w+4]*sc[w+4];
                        V[3][w] = V[3][w-1] - tc[w-1]*tc[w-1] + tc[w+4]*tc[w+4];
                        V[4][w] = V[4][w-1] - sc[w-1]*tc[w-1] + sc[w+4]*tc[w+4];
                    }
                }
                if (pl == 0) {
                    #pragma unroll
                    for (int c = 0; c < 5; c++) {
                        keep[c][0] = __floats2half2_rn(V[c][0], V[c][1]);
                        keep[c][1] = __floats2half2_rn(V[c][2], V[c][3]);
                    }
                } else {
                    #pragma unroll
                    for (int c = 0; c < 5; c++) {
                        union { __half2 h[4]; uint4 u; } pk;
                        pk.h[0] = keep[c][0];
                        pk.h[1] = __floats2half2_rn(V[c][0], V[c][1]);
                        pk.h[2] = keep[c][1];
                        pk.h[3] = __floats2half2_rn(V[c][2], V[c][3]);
                        *reinterpret_cast<uint4*>(rsq + c * RSCH + r * RSROW + 4 * g)
                            = pk.u;
                    }
                }
            }
        };

        issue_pair(0);
        issue_pair(1);

        for (int k = 0; k < NPAIRS; k++) {
            const int q = k & 1;
            bar_sync_n(BAR_EMPTY0 + q, NTHREADS);
            issue_pair(k + 2);
            cp_wait2();
            bar_sync_n(BAR_PROD, NPROD);

            if (tid < 96)
                xpair(&tile[k % 3][0][0][0][0], &rs[q][0], tid);

            bar_arrive_n(BAR_FULL0 + q, NTHREADS);
        }
    } else {
        // ===================== CONSUMER (64), 4 px each =====================
        // owns output rows 2*cyp, 2*cyp+1 at x-pair cx2
        const int ctid = tid - NPROD;            // 0..63
        const int cx2  = ctid & 15;
        const int cyp  = ctid >> 4;              // 0..3
        const int cbase = (2 * cyp) * RSROW + cx2 * 2;

        // half2 delay-line ring (bit-exact telescoping: identical f16->f32
        // convert on entry and exit), fp32 running sums
        __half2 ring[5][2][5];                   // [slot][row][ch]
        float2  run[2][5];                       // [row][ch] (x-pair packed)
        const __half2 hzz = __floats2half2_rn(0.f, 0.f);
        #pragma unroll
        for (int s = 0; s < 5; s++)
            #pragma unroll
            for (int r = 0; r < 2; r++)
                #pragma unroll
                for (int c = 0; c < 5; c++) ring[s][r][c] = hzz;
        #pragma unroll
        for (int r = 0; r < 2; r++)
            #pragma unroll
            for (int c = 0; c < 5; c++) run[r][c] = make_float2(0.f, 0.f);

        bar_arrive_n(BAR_EMPTY0, NTHREADS);
        bar_arrive_n(BAR_EMPTY1, NTHREADS);

        auto upd = [&](int r, int c, int s, __half2 n) {
            float2 f = __half22float2(n);
            float2 o = __half22float2(ring[s][r][c]);
            run[r][c].x += f.x - o.x;
            run[r][c].y += f.y - o.y;
            ring[s][r][c] = n;
        };
        auto epilogue = [&](int r) {
            const float inv = 1.f / 125.f;
            #pragma unroll
            for (int e = 0; e < 2; e++) {
                float rS  = e ? run[r][0].y : run[r][0].x;
                float rT  = e ? run[r][1].y : run[r][1].x;
                float rSS = e ? run[r][2].y : run[r][2].x;
                float rTT = e ? run[r][3].y : run[r][3].x;
                float rST = e ? run[r][4].y : run[r][4].x;
                float sm = rS * inv;
                float tm = rT * inv;
                float sv = fmaf(-sm, sm, rSS * inv);
                float tv = fmaf(-tm, tm, rTT * inv);
                float cr = fmaf(-sm, tm, rST * inv);
                float den = fmaf(sv, tv, 1e-5f);
                acc += __fdividef(cr * cr, den);
            }
        };

        // consume both planes of pair k; slots s0 (plane 2k), s1 (plane 2k+1)
        auto consume_pair = [&](const __half2* rq, int s0, int s1, bool live) {
            __half2 a1[5], b1[5];                // plane1 y-sums (rows 0,1)
            #pragma unroll
            for (int c = 0; c < 5; c++) {
                const __half2* col = rq + c * RSCH + cbase;
                __half2 p0,p1, q0,q1, r0,r1, u0,u1, t0,t1, w0,w1;
                lds_h2x2(col + 0 * RSROW, p0, p1);
                lds_h2x2(col + 1 * RSROW, q0, q1);
                lds_h2x2(col + 2 * RSROW, r0, r1);
                lds_h2x2(col + 3 * RSROW, u0, u1);
                lds_h2x2(col + 4 * RSROW, t0, t1);
                lds_h2x2(col + 5 * RSROW, w0, w1);
                // plane 0 y-sums: rows cyp*2 and cyp*2+1
                __half2 nA = __hadd2(__hadd2(__hadd2(p0, q0),
                                             __hadd2(r0, u0)), t0);
                __half2 nB = __hadd2(__hsub2(nA, p0), w0);
                upd(0, c, s0, nA);
                upd(1, c, s0, nB);
                // plane 1 stash
                a1[c] = __hadd2(__hadd2(__hadd2(p1, q1), __hadd2(r1, u1)), t1);
                b1[c] = __hadd2(__hsub2(a1[c], p1), w1);
            }
            if (live) { epilogue(0); epilogue(1); }      // plane 2k
            #pragma unroll
            for (int c = 0; c < 5; c++) {
                upd(0, c, s1, a1[c]);
                upd(1, c, s1, b1[c]);
            }
            if (live) { epilogue(0); epilogue(1); }      // plane 2k+1
        };

        for (int kb = 0; kb <= 80; kb += 5) {
            #pragma unroll
            for (int jj = 0; jj < 5; jj++) {
                const int k = kb + jj;
                if (k >= NPAIRS) break;          // 82 = 16*5 + 2
                const int q  = k & 1;
                const int s0 = (2 * jj) % 5;     // kb % 5 == 0
                const int s1 = (2 * jj + 1) % 5;
                bar_sync_n(BAR_FULL0 + q, NTHREADS);
                consume_pair(&rs[q][0], s0, s1, k >= 2);
                bar_arrive_n(BAR_EMPTY0 + q, NTHREADS);
            }
        }
    }

    // ---- block reduction over all 192 threads (producers contribute 0) ----
    __syncthreads();
    #pragma unroll
    for (int o = 16; o > 0; o >>= 1)
        acc += __shfl_xor_sync(0xffffffffu, acc, o);
    if ((tid & 31) == 0) wsum[tid >> 5] = acc;
    __syncthreads();

    if (tid == 0) {
        float bsum = 0.f;
        #pragma unroll
        for (int i = 0; i < 6; i++) bsum += wsum[i];
        atomicAdd(&g_acc, (double)bsum);
        __threadfence();
        unsigned done = atomicAdd(&g_cnt, 1u);
        if (done == NBLOCKS - 1) {
            double total = atomicAdd(&g_acc, 0.0);  // fenced read
            const double n = 2.0 * 160.0 * 192.0 * 192.0;
            float loss = (float)(1.0 - total / n);
            if (isnan(loss) || isinf(loss)) loss = 1.0f;
            out[0] = loss;
            *((volatile double*)&g_acc)   = 0.0;
            *((volatile unsigned*)&g_cnt) = 0u;
        }
    }
}

extern "C" void kernel_launch(void* const* d_in, const int* in_sizes, int n_in,
                              void* d_out, int out_size)
{
    (void)in_sizes; (void)n_in; (void)out_size;
    const float* src = (const float*)d_in[0];
    const float* tgt = (const float*)d_in[1];

    lncc_k<<<dim3(6, 24, 2), NTHREADS>>>(src, tgt, (float*)d_out);
}

// round 15
// speedup vs baseline: 1.2539x; 1.2539x over previous
#include <cuda_runtime.h>
#include <cuda_fp16.h>
#include <math.h>
#include <stdint.h>

#define W_ 192
#define H_ 192
#define D_ 160
#define HW_ (H_ * W_)
#define NPAIRS  82             /* 164 planes = D + 4 halo */
#define NBLOCKS (6 * 24 * 2)

#define NTHREADS 256
#define NPROD    128

#define BAR_FULL0  1
#define BAR_FULL1  2
#define BAR_EMPTY0 3
#define BAR_EMPTY1 4
#define BAR_PROD   5

// tile geometry: 32 x 8 outputs, halo 36 x 12
#define HROWS 12
#define TROWF 480              /* floats per img plane: 12*40 */
#define TPLANEF 960            /* floats per plane (2 imgs) */
#define TPAIRF 1920            /* floats per pair buffer */
#define NPAIRS_LD 432          /* 12*18*2 8B pairs per plane */

// rs layout (plane-interleaved): [ch(5)][row(12)][x2(16)][plane(2)] of __half2
#define RSCH 384
#define RSROW 32
#define RSQ 1920

typedef unsigned long long ull;

__device__ double   g_acc;
__device__ unsigned g_cnt;

static __device__ __forceinline__ void bar_sync_n(int id, int cnt) {
    asm volatile("bar.sync %0, %1;" :: "r"(id), "r"(cnt) : "memory");
}
static __device__ __forceinline__ void bar_arrive_n(int id, int cnt) {
    asm volatile("bar.arrive %0, %1;" :: "r"(id), "r"(cnt) : "memory");
}
static __device__ __forceinline__ void cp_async8(uint32_t dst, const float* src,
                                                 unsigned srcsz) {
    asm volatile("cp.async.ca.shared.global [%0], [%1], 8, %2;"
                 :: "r"(dst), "l"(src), "r"(srcsz) : "memory");
}
static __device__ __forceinline__ void cp_commit() {
    asm volatile("cp.async.commit_group;" ::: "memory");
}
static __device__ __forceinline__ void cp_wait2() {
    asm volatile("cp.async.wait_group 2;" ::: "memory");
}
// 8B shared load of two adjacent half2 (plane0, plane1)
static __device__ __forceinline__ void lds_h2x2(const __half2* p,
                                                __half2& a, __half2& b) {
    uint2 u = *reinterpret_cast<const uint2*>(p);
    a = *reinterpret_cast<__half2*>(&u.x);
    b = *reinterpret_cast<__half2*>(&u.y);
}
// ---- packed f32x2 helpers (sm_103a FFMA2 path, PTX-only) ----
static __device__ __forceinline__ ull pk2(float x, float y) {
    ull r; asm("mov.b64 %0, {%1, %2};" : "=l"(r) : "f"(x), "f"(y)); return r;
}
static __device__ __forceinline__ float2 upk2(ull v) {
    float2 r; asm("mov.b64 {%0, %1}, %2;" : "=f"(r.x), "=f"(r.y) : "l"(v)); return r;
}
static __device__ __forceinline__ ull add2(ull a, ull b) {
    ull r; asm("add.rn.f32x2 %0, %1, %2;" : "=l"(r) : "l"(a), "l"(b)); return r;
}
static __device__ __forceinline__ ull mul2(ull a, ull b) {
    ull r; asm("mul.rn.f32x2 %0, %1, %2;" : "=l"(r) : "l"(a), "l"(b)); return r;
}
static __device__ __forceinline__ ull fma2(ull a, ull b, ull c) {
    ull r; asm("fma.rn.f32x2 %0, %1, %2, %3;" : "=l"(r) : "l"(a), "l"(b), "l"(c));
    return r;
}
static __device__ __forceinline__ ull h2_to_f32x2(__half2 h) {
    float2 f = __half22float2(h);
    return pk2(f.x, f.y);
}

__global__ void __launch_bounds__(NTHREADS, 2)
lncc_k(const float* __restrict__ src, const float* __restrict__ tgt,
       float* __restrict__ out)
{
    __shared__ float tile[3][2][2][HROWS][40];
    __shared__ __align__(16) __half2 rs[2][RSQ];
    __shared__ float wsum[8];

    const int tid = threadIdx.x;
    const int x0  = blockIdx.x * 32;
    const int y0  = blockIdx.y * 8;
    const int b   = blockIdx.z;          // one z-chunk covers all of D
    const int zstart = -2;

    const float* baseS = src + (size_t)b * (D_ * HW_);
    const float* baseT = tgt + (size_t)b * (D_ * HW_);

    float acc = 0.f;

    if (tid < NPROD) {
        // ========================= PRODUCER (128) =========================
        uint32_t soffb[4];
        const float* gbase[4];
        unsigned vmask = 0, umask = 0;
        #pragma unroll
        for (int sl = 0; sl < 4; sl++) {
            soffb[sl] = 0; gbase[sl] = baseS;
            const int i = tid + NPROD * sl;
            if (i < NPAIRS_LD) {
                umask |= 1u << sl;
                const int img = (i >= 216) ? 1 : 0;
                const int j   = i - img * 216;
                const int row = j / 18;
                const int pc  = j - row * 18;
                soffb[sl] = (uint32_t)(img * TROWF + row * 40 + pc * 2) * 4u;
                const int gy = y0 + row - 2;
                const int gx = x0 + pc * 2 - 2;
                const bool v = ((unsigned)gy < (unsigned)H_) &&
                               ((unsigned)gx < (unsigned)W_);
                if (v) vmask |= 1u << sl;
                gbase[sl] = (img ? baseT : baseS) + (v ? (gy * W_ + gx) : 0);
            }
        }

        const uint32_t sbase =
            (uint32_t)__cvta_generic_to_shared(&tile[0][0][0][0][0]);

        auto issue_pair = [&](int m) {
            const uint32_t pb = sbase + (uint32_t)(m % 3) * (TPAIRF * 4u);
            #pragma unroll
            for (int pl = 0; pl < 2; pl++) {
                const int zp   = zstart + 2 * m + pl;
                const bool zin = (unsigned)zp < (unsigned)D_;
                const int zoff = zin ? zp * HW_ : 0;
                const uint32_t tb = pb + (uint32_t)pl * (TPLANEF * 4u);
                #pragma unroll
                for (int sl = 0; sl < 4; sl++) {
                    if (umask & (1u << sl)) {
                        unsigned sz = (zin && (vmask & (1u << sl))) ? 8u : 0u;
                        cp_async8(tb + soffb[sl], gbase[sl] + zoff, sz);
                    }
                }
            }
            cp_commit();
        };

        // x-phase item covering BOTH planes of (row r, group g)
        auto xpair = [&](const float* pbuf, __half2* rsq, int item) {
            const int r = item >> 3;
            const int g = item & 7;
            const float* base0 = pbuf + r * 40 + 4 * g;
            __half2 keep[5][2];
            #pragma unroll
            for (int pl = 0; pl < 2; pl++) {
                const float* rowS = base0 + pl * TPLANEF;
                const float* rowT = rowS + TROWF;
                float4 a0 = *(const float4*)(rowS);
                float4 a1 = *(const float4*)(rowS + 4);
                float4 b0 = *(const float4*)(rowT);
                float4 b1 = *(const float4*)(rowT + 4);
                float sc[8] = {a0.x,a0.y,a0.z,a0.w,a1.x,a1.y,a1.z,a1.w};
                float tc[8] = {b0.x,b0.y,b0.z,b0.w,b1.x,b1.y,b1.z,b1.w};

                float V[5][4];
                {
                    float S0=0.f, T0=0.f, SS0=0.f, TT0=0.f, ST0=0.f;
                    #pragma unroll
                    for (int j = 0; j < 5; j++) {
                        S0 += sc[j]; T0 += tc[j];
                        SS0 = fmaf(sc[j], sc[j], SS0);
                        TT0 = fmaf(tc[j], tc[j], TT0);
                        ST0 = fmaf(sc[j], tc[j], ST0);
                    }
                    V[0][0]=S0; V[1][0]=T0; V[2][0]=SS0; V[3][0]=TT0; V[4][0]=ST0;
                    #pragma unroll
                    for (int w = 1; w < 4; w++) {
                        V[0][w] = V[0][w-1] - sc[w-1] + sc[w+4];
                        V[1][w] = V[1][w-1] - tc[w-1] + tc[w+4];
                        V[2][w] = V[2][w-1] - sc[w-1]*sc[w-1] + sc[w+4]*sc[w+4];
                        V[3][w] = V[3][w-1] - tc[w-1]*tc[w-1] + tc[w+4]*tc[w+4];
                        V[4][w] = V[4][w-1] - sc[w-1]*tc[w-1] + sc[w+4]*tc[w+4];
                    }
                }
                if (pl == 0) {
                    #pragma unroll
                    for (int c = 0; c < 5; c++) {
                        keep[c][0] = __floats2half2_rn(V[c][0], V[c][1]);
                        keep[c][1] = __floats2half2_rn(V[c][2], V[c][3]);
                    }
                } else {
                    #pragma unroll
                    for (int c = 0; c < 5; c++) {
                        union { __half2 h[4]; uint4 u; } pk;
                        pk.h[0] = keep[c][0];
                        pk.h[1] = __floats2half2_rn(V[c][0], V[c][1]);
                        pk.h[2] = keep[c][1];
                        pk.h[3] = __floats2half2_rn(V[c][2], V[c][3]);
                        *reinterpret_cast<uint4*>(rsq + c * RSCH + r * RSROW + 4 * g)
                            = pk.u;
                    }
                }
            }
        };

        issue_pair(0);
        issue_pair(1);

        for (int k = 0; k < NPAIRS; k++) {
            const int q = k & 1;
            bar_sync_n(BAR_EMPTY0 + q, NTHREADS);
            issue_pair(k + 2);
            cp_wait2();
            bar_sync_n(BAR_PROD, NPROD);

            if (tid < 96)
                xpair(&tile[k % 3][0][0][0][0], &rs[q][0], tid);

            bar_arrive_n(BAR_FULL0 + q, NTHREADS);
        }
    } else {
        // ========================= CONSUMER (128) =========================
        // thread owns x-pair (2*ctx2, 2*ctx2+1) at output row cty
        const int ctid = tid - NPROD;
        const int ctx2 = ctid & 15;
        const int cty  = ctid >> 4;
        const int cbase = cty * RSROW + ctx2 * 2;

        // half2 delay-line ring (bit-exact: identical f16->f32 convert on
        // entry and exit), packed-f32x2 running sums
        __half2 ring[5][5];                  // [slot][ch]
        ull run[5];                          // [ch], packed f32x2 over x-pair
        const __half2 hzz = __floats2half2_rn(0.f, 0.f);
        #pragma unroll
        for (int s = 0; s < 5; s++)
            #pragma unroll
            for (int c = 0; c < 5; c++) ring[s][c] = hzz;
        #pragma unroll
        for (int c = 0; c < 5; c++) run[c] = pk2(0.f, 0.f);

        const ull NEG1 = pk2(-1.f, -1.f);
        const ull INV2 = pk2(1.f / 125.f, 1.f / 125.f);
        const ull EPS2 = pk2(1e-5f, 1e-5f);

        bar_arrive_n(BAR_EMPTY0, NTHREADS);
        bar_arrive_n(BAR_EMPTY1, NTHREADS);

        auto epilogue = [&]() {
            ull sm = mul2(run[0], INV2);
            ull tm = mul2(run[1], INV2);
            ull nsm = mul2(sm, NEG1);
            ull sv = fma2(nsm, sm, mul2(run[2], INV2));
            ull tv = fma2(mul2(tm, NEG1), tm, mul2(run[3], INV2));
            ull cr = fma2(nsm, tm, mul2(run[4], INV2));
            ull den = fma2(sv, tv, EPS2);
            ull cr2 = mul2(cr, cr);
            float2 cnum = upk2(cr2);
            float2 cden = upk2(den);
            acc += __fdividef(cnum.x, cden.x);
            acc += __fdividef(cnum.y, cden.y);
        };

        // consume both planes of pair k; slots s0 (plane 2k), s1 (plane 2k+1)
        auto consume_pair = [&](const __half2* rq, int s0, int s1, bool live) {
            __half2 stash1[5];
            #pragma unroll
            for (int c = 0; c < 5; c++) {
                const __half2* col = rq + c * RSCH + cbase;
                __half2 p0, p1, q0, q1;
                lds_h2x2(col + 0 * RSROW, p0, p1);
                lds_h2x2(col + 1 * RSROW, q0, q1);
                __half2 n0 = __hadd2(p0, q0);
                __half2 n1 = __hadd2(p1, q1);
                lds_h2x2(col + 2 * RSROW, p0, p1);
                lds_h2x2(col + 3 * RSROW, q0, q1);
                n0 = __hadd2(n0, __hadd2(p0, q0));
                n1 = __hadd2(n1, __hadd2(p1, q1));
                lds_h2x2(col + 4 * RSROW, p0, p1);
                n0 = __hadd2(n0, p0);
                n1 = __hadd2(n1, p1);
                // plane 2k ring update (slot s0): run += f - old (packed)
                ull f = h2_to_f32x2(n0);
                ull o = h2_to_f32x2(ring[s0][c]);
                run[c] = add2(run[c], fma2(o, NEG1, f));
                ring[s0][c] = n0;
                stash1[c] = n1;
            }
            if (live) epilogue();            // plane 2k
            #pragma unroll
            for (int c = 0; c < 5; c++) {
                ull f = h2_to_f32x2(stash1[c]);
                ull o = h2_to_f32x2(ring[s1][c]);
                run[c] = add2(run[c], fma2(o, NEG1, f));
                ring[s1][c] = stash1[c];
            }
            if (live) epilogue();            // plane 2k+1
        };

        for (int kb = 0; kb <= 80; kb += 5) {
            #pragma unroll
            for (int jj = 0; jj < 5; jj++) {
                const int k = kb + jj;
                if (k >= NPAIRS) break;      // 82 = 16*5 + 2
                const int q  = k & 1;
                const int s0 = (2 * jj) % 5;     // kb % 5 == 0
                const int s1 = (2 * jj + 1) % 5;
                bar_sync_n(BAR_FULL0 + q, NTHREADS);
                consume_pair(&rs[q][0], s0, s1, k >= 2);
                bar_arrive_n(BAR_EMPTY0 + q, NTHREADS);
            }
        }
    }

    // ---- block reduction over all 256 threads (producers contribute 0) ----
    __syncthreads();
    #pragma unroll
    for (int o = 16; o > 0; o >>= 1)
        acc += __shfl_xor_sync(0xffffffffu, acc, o);
    if ((tid & 31) == 0) wsum[tid >> 5] = acc;
    __syncthreads();

    if (tid == 0) {
        float bsum = 0.f;
        #pragma unroll
        for (int i = 0; i < 8; i++) bsum += wsum[i];
        atomicAdd(&g_acc, (double)bsum);
        __threadfence();
        unsigned done = atomicAdd(&g_cnt, 1u);
        if (done == NBLOCKS - 1) {
            double total = atomicAdd(&g_acc, 0.0);  // fenced read
            const double n = 2.0 * 160.0 * 192.0 * 192.0;
            float loss = (float)(1.0 - total / n);
            if (isnan(loss) || isinf(loss)) loss = 1.0f;
            out[0] = loss;
            *((volatile double*)&g_acc)   = 0.0;
            *((volatile unsigned*)&g_cnt) = 0u;
        }
    }
}

extern "C" void kernel_launch(void* const* d_in, const int* in_sizes, int n_in,
                              void* d_out, int out_size)
{
    (void)in_sizes; (void)n_in; (void)out_size;
    const float* src = (const float*)d_in[0];
    const float* tgt = (const float*)d_in[1];

    lncc_k<<<dim3(6, 24, 2), NTHREADS>>>(src, tgt, (float*)d_out);
}